// round 1
// baseline (speedup 1.0000x reference)
#include <cuda_runtime.h>
#include <cuda_bf16.h>

#define MAXN 100000
#define MAXE 1600000

// ---------------- scratch (device globals; allocation-free) ----------------
__device__ __align__(16) float g_h1[MAXN * 128];    // layer1 features h = x@W1
__device__ __align__(16) float g_acc1[MAXN * 128];  // layer1 accumulator, then z (elu) in-place
__device__ __align__(16) float g_h2[MAXN * 64];     // layer2 features h2 = z@W2
__device__ __align__(16) float g_acc2[MAXN * 64];   // layer2 accumulator, then z2 in-place
__device__ float g_as1[MAXN * 2];
__device__ float g_ad1[MAXN * 2];
__device__ float g_den1[MAXN * 2];
__device__ float g_as2[MAXN];
__device__ float g_ad2[MAXN];
__device__ float g_den2[MAXN];
__device__ float g_ee1[(MAXE + MAXN) * 2];
__device__ float g_ee2[(MAXE + MAXN)];

// ---------------- init ----------------
__global__ void init_kernel(int N) {
    int i = blockIdx.x * blockDim.x + threadIdx.x;
    if (i < N * 128) g_acc1[i] = 0.f;
    if (i < N * 64)  g_acc2[i] = 0.f;
    if (i < N * 2)   g_den1[i] = 0.f;
    if (i < N)       g_den2[i] = 0.f;
}

// ---------------- fp32 GEMM: Y[N,NC] = X[N,128] @ W[128,NC] ----------------
// tile: 128 rows x NC cols, K=128 fully resident in smem; 256 threads; 8 x (NC/16) micro-tile.
template <int NC>
__global__ void gemm_kernel(const float* __restrict__ X, const float* __restrict__ W,
                            float* __restrict__ Y, int N) {
    extern __shared__ float smem[];
    float* Xs = smem;               // 128 x 128
    float* Ws = smem + 128 * 128;   // 128 x NC
    const int tid = threadIdx.x;
    const int row0 = blockIdx.x * 128;

    for (int i = tid * 4; i < 128 * NC; i += 256 * 4)
        *(float4*)&Ws[i] = *(const float4*)&W[i];
    for (int i = tid * 4; i < 128 * 128; i += 256 * 4) {
        int r = i >> 7;
        int gr = row0 + r;
        float4 v = make_float4(0.f, 0.f, 0.f, 0.f);
        if (gr < N) v = *(const float4*)&X[gr * 128 + (i & 127)];
        *(float4*)&Xs[i] = v;
    }
    __syncthreads();

    constexpr int MC = NC / 16;
    const int tx = tid & 15, ty = tid >> 4;
    const int r0 = ty * 8, c0 = tx * MC;
    float acc[8][MC];
#pragma unroll
    for (int i = 0; i < 8; i++)
#pragma unroll
        for (int j = 0; j < MC; j++) acc[i][j] = 0.f;

#pragma unroll 4
    for (int k = 0; k < 128; k++) {
        float b[MC];
#pragma unroll
        for (int j4 = 0; j4 < MC; j4 += 4)
            *(float4*)&b[j4] = *(const float4*)&Ws[k * NC + c0 + j4];
#pragma unroll
        for (int i = 0; i < 8; i++) {
            float a = Xs[(r0 + i) * 128 + k];
#pragma unroll
            for (int j = 0; j < MC; j++) acc[i][j] = fmaf(a, b[j], acc[i][j]);
        }
    }

#pragma unroll
    for (int i = 0; i < 8; i++) {
        int gr = row0 + r0 + i;
        if (gr < N) {
#pragma unroll
            for (int j4 = 0; j4 < MC; j4 += 4)
                *(float4*)&Y[gr * NC + c0 + j4] = *(const float4*)&acc[i][j4];
        }
    }
}

// ---------------- attention logits: alpha_s/alpha_d per (node, head) ----------------
// 16-lane group per (node,head); C=64 always.
__global__ void alpha_kernel(const float* __restrict__ h, const float* __restrict__ a_src,
                             const float* __restrict__ a_dst, float* __restrict__ out_s,
                             float* __restrict__ out_d, int N, int NH) {
    int t = blockIdx.x * blockDim.x + threadIdx.x;
    int g = t >> 4, li = t & 15;
    if (g >= N * NH) return;
    int head = (NH == 2) ? (g & 1) : 0;  // g = node*NH + head layout
    // note: g already equals node*NH+head; feature base = g*64
    float4 hv = *(const float4*)&h[g * 64 + li * 4];
    float4 s4 = *(const float4*)&a_src[head * 64 + li * 4];
    float4 d4 = *(const float4*)&a_dst[head * 64 + li * 4];
    float s = hv.x * s4.x + hv.y * s4.y + hv.z * s4.z + hv.w * s4.w;
    float d = hv.x * d4.x + hv.y * d4.y + hv.z * d4.z + hv.w * d4.w;
#pragma unroll
    for (int o = 8; o; o >>= 1) {
        s += __shfl_down_sync(0xffffffffu, s, o, 16);
        d += __shfl_down_sync(0xffffffffu, d, o, 16);
    }
    if (li == 0) {
        out_s[g] = s;
        out_d[g] = d;
    }
}

// ---------------- edge pass A: ee = exp(leakyrelu(as[src]+ad[dst])), denom scatter ----------------
template <int NH>
__global__ void edge_ee_kernel(const int* __restrict__ esrc, const int* __restrict__ edst,
                               int E, int N, const float* __restrict__ as,
                               const float* __restrict__ ad, float* __restrict__ ee,
                               float* __restrict__ den) {
    int t = blockIdx.x * blockDim.x + threadIdx.x;
    int e, h;
    if (NH == 2) { e = t >> 1; h = t & 1; } else { e = t; h = 0; }
    if (e >= E + N) return;
    int src, dst;
    if (e < E) { src = esrc[e]; dst = edst[e]; }
    else       { src = dst = e - E; }
    float v = as[src * NH + h] + ad[dst * NH + h];
    v = v > 0.f ? v : 0.2f * v;
    float ev = __expf(v);
    ee[e * NH + h] = ev;
    atomicAdd(&den[dst * NH + h], ev);
}

// ---------------- edge pass B (layer1): warp per edge, 128 feats, float4 atomics ----------------
__global__ void edge_agg1_kernel(const int* __restrict__ esrc, const int* __restrict__ edst,
                                 int E, int N) {
    int t = blockIdx.x * blockDim.x + threadIdx.x;
    int w = t >> 5, lane = t & 31;
    if (w >= E + N) return;
    int src, dst;
    if (w < E) { src = esrc[w]; dst = edst[w]; }
    else       { src = dst = w - E; }
    float a = g_ee1[w * 2 + (lane >> 4)];
    float4 v = *(const float4*)&g_h1[src * 128 + lane * 4];
    v.x *= a; v.y *= a; v.z *= a; v.w *= a;
    atomicAdd((float4*)&g_acc1[dst * 128 + lane * 4], v);
}

// ---------------- edge pass B (layer2): 16-lane group per edge, 64 feats ----------------
__global__ void edge_agg2_kernel(const int* __restrict__ esrc, const int* __restrict__ edst,
                                 int E, int N) {
    int t = blockIdx.x * blockDim.x + threadIdx.x;
    int g = t >> 4, li = t & 15;
    if (g >= E + N) return;
    int src, dst;
    if (g < E) { src = esrc[g]; dst = edst[g]; }
    else       { src = dst = g - E; }
    float a = g_ee2[g];
    float4 v = *(const float4*)&g_h2[src * 64 + li * 4];
    v.x *= a; v.y *= a; v.z *= a; v.w *= a;
    atomicAdd((float4*)&g_acc2[dst * 64 + li * 4], v);
}

// ---------------- finalize layer1: z = elu(acc/den + b1), in place ----------------
__global__ void fin1_kernel(const float* __restrict__ b1, int N) {
    int i = blockIdx.x * blockDim.x + threadIdx.x;
    if (i >= N * 128) return;
    int n = i >> 7, c = i & 127;
    float v = g_acc1[i] / g_den1[n * 2 + (c >> 6)] + b1[c];
    g_acc1[i] = v > 0.f ? v : (__expf(v) - 1.f);
}

// ---------------- finalize layer2: z2 = acc2/den2 + b2, in place ----------------
__global__ void fin2_kernel(const float* __restrict__ b2, int N) {
    int i = blockIdx.x * blockDim.x + threadIdx.x;
    if (i >= N * 64) return;
    int n = i >> 6, c = i & 63;
    g_acc2[i] = g_acc2[i] / g_den2[n] + b2[c];
}

// ---------------- decode: dot(z2[a], z2[b]) over 64 ----------------
__global__ void decode_kernel(const int* __restrict__ eli, int EL, float* __restrict__ out) {
    int t = blockIdx.x * blockDim.x + threadIdx.x;
    int g = t >> 4, li = t & 15;
    if (g >= EL) return;
    int a = eli[g];
    int b = eli[EL + g];
    float4 va = *(const float4*)&g_acc2[a * 64 + li * 4];
    float4 vb = *(const float4*)&g_acc2[b * 64 + li * 4];
    float s = va.x * vb.x + va.y * vb.y + va.z * vb.z + va.w * vb.w;
#pragma unroll
    for (int o = 8; o; o >>= 1) s += __shfl_down_sync(0xffffffffu, s, o, 16);
    if (li == 0) out[g] = s;
}

// ---------------- launcher ----------------
extern "C" void kernel_launch(void* const* d_in, const int* in_sizes, int n_in,
                              void* d_out, int out_size) {
    const float* x   = (const float*)d_in[0];
    const int*   eidx = (const int*)d_in[1];
    const int*   eli  = (const int*)d_in[2];
    const float* W1  = (const float*)d_in[3];
    const float* as1 = (const float*)d_in[4];
    const float* ad1 = (const float*)d_in[5];
    const float* b1  = (const float*)d_in[6];
    const float* W2  = (const float*)d_in[7];
    const float* as2 = (const float*)d_in[8];
    const float* ad2 = (const float*)d_in[9];
    const float* b2  = (const float*)d_in[10];
    float* out = (float*)d_out;

    const int N  = in_sizes[0] / 128;
    const int E  = in_sizes[1] / 2;
    const int EL = in_sizes[2] / 2;
    const int* esrc = eidx;
    const int* edst = eidx + E;

    // opt into >48KB dynamic smem for the GEMMs (idempotent, capture-safe)
    cudaFuncSetAttribute(gemm_kernel<128>, cudaFuncAttributeMaxDynamicSharedMemorySize, 131072);
    cudaFuncSetAttribute(gemm_kernel<64>,  cudaFuncAttributeMaxDynamicSharedMemorySize,  98304);

    float *ph1, *pacc1, *ph2, *pas1, *pad1, *pden1, *pas2, *pad2, *pden2, *pee1, *pee2;
    cudaGetSymbolAddress((void**)&ph1,   g_h1);
    cudaGetSymbolAddress((void**)&pacc1, g_acc1);
    cudaGetSymbolAddress((void**)&ph2,   g_h2);
    cudaGetSymbolAddress((void**)&pas1,  g_as1);
    cudaGetSymbolAddress((void**)&pad1,  g_ad1);
    cudaGetSymbolAddress((void**)&pden1, g_den1);
    cudaGetSymbolAddress((void**)&pas2,  g_as2);
    cudaGetSymbolAddress((void**)&pad2,  g_ad2);
    cudaGetSymbolAddress((void**)&pden2, g_den2);
    cudaGetSymbolAddress((void**)&pee1,  g_ee1);
    cudaGetSymbolAddress((void**)&pee2,  g_ee2);

    const int B = 256;
    auto cdiv = [](long long a, long long b) { return (int)((a + b - 1) / b); };

    // 1) zero accumulators / denominators
    init_kernel<<<cdiv((long long)N * 128, B), B>>>(N);

    // 2) h1 = x @ W1
    gemm_kernel<128><<<cdiv(N, 128), 256, 131072>>>(x, W1, ph1, N);

    // 3) per-node logits (layer1, 2 heads)
    alpha_kernel<<<cdiv((long long)N * 2 * 16, B), B>>>(ph1, as1, ad1, pas1, pad1, N, 2);

    // 4) edge exp + denom (layer1)
    edge_ee_kernel<2><<<cdiv((long long)(E + N) * 2, B), B>>>(esrc, edst, E, N, pas1, pad1, pee1, pden1);

    // 5) edge aggregate (layer1): warp per edge
    edge_agg1_kernel<<<cdiv((long long)(E + N) * 32, B), B>>>(esrc, edst, E, N);

    // 6) z = elu(acc/den + b1)
    fin1_kernel<<<cdiv((long long)N * 128, B), B>>>(b1, N);

    // 7) h2 = z @ W2
    gemm_kernel<64><<<cdiv(N, 128), 256, 98304>>>(pacc1, W2, ph2, N);

    // 8) per-node logits (layer2, 1 head)
    alpha_kernel<<<cdiv((long long)N * 16, B), B>>>(ph2, as2, ad2, pas2, pad2, N, 1);

    // 9) edge exp + denom (layer2)
    edge_ee_kernel<1><<<cdiv((long long)(E + N), B), B>>>(esrc, edst, E, N, pas2, pad2, pee2, pden2);

    // 10) edge aggregate (layer2): 16 lanes per edge
    edge_agg2_kernel<<<cdiv((long long)(E + N) * 16, B), B>>>(esrc, edst, E, N);

    // 11) z2 = acc2/den2 + b2
    fin2_kernel<<<cdiv((long long)N * 64, B), B>>>(b2, N);

    // 12) decode
    decode_kernel<<<cdiv((long long)EL * 16, B), B>>>(eli, EL, out);
}

// round 2
// speedup vs baseline: 1.5542x; 1.5542x over previous
#include <cuda_runtime.h>
#include <cuda_bf16.h>

#define MAXN 100000
#define MAXE 1600000
typedef unsigned long long u64;

// ---------------- scratch (device globals; allocation-free) ----------------
__device__ __align__(16) float g_h1[MAXN * 128];    // layer1 features h = x@W1
__device__ __align__(16) float g_z1[MAXN * 128];    // layer1 output z = elu(agg + b1)
__device__ __align__(16) float g_h2[MAXN * 64];     // layer2 features h2 = z@W2
__device__ __align__(16) float g_z2[MAXN * 64];     // layer2 output z2
__device__ float g_as1[MAXN * 2];
__device__ float g_ad1[MAXN * 2];
__device__ float g_as2[MAXN];
__device__ float g_ad2[MAXN];
__device__ __align__(8) float g_ee1[(MAXE + MAXN) * 2];  // CSR-ordered exp(logit), 2 heads
__device__ int g_deg[MAXN];
__device__ int g_rowstart[MAXN + 1];
__device__ int g_cursor[MAXN];
__device__ int g_part[256];
__device__ int g_csr_src[MAXE + MAXN];

// ---------------- f32x2 packed helpers ----------------
__device__ __forceinline__ u64 pack2(float lo, float hi) {
    u64 r;
    asm("mov.b64 %0, {%1, %2};" : "=l"(r) : "f"(lo), "f"(hi));
    return r;
}
__device__ __forceinline__ void unpack2(u64 v, float& lo, float& hi) {
    asm("mov.b64 {%0, %1}, %2;" : "=f"(lo), "=f"(hi) : "l"(v));
}
__device__ __forceinline__ void fma2(u64& d, u64 a, u64 b) {
    asm("fma.rn.f32x2 %0, %1, %2, %0;" : "+l"(d) : "l"(a), "l"(b));
}

// ---------------- CSR build ----------------
__global__ void zero_deg_kernel(int N) {
    int i = blockIdx.x * blockDim.x + threadIdx.x;
    if (i < N) g_deg[i] = 0;
}

__global__ void hist_kernel(const int* __restrict__ edst, int E, int N) {
    int t = blockIdx.x * blockDim.x + threadIdx.x;
    if (t >= E + N) return;
    int dst = (t < E) ? edst[t] : (t - E);
    atomicAdd(&g_deg[dst], 1);
}

// block-level exclusive scan (1024 elems/block)
__global__ void scan1_kernel(int N) {
    __shared__ int sm[1024];
    int i = blockIdx.x * 1024 + threadIdx.x;
    int v = (i < N) ? g_deg[i] : 0;
    sm[threadIdx.x] = v;
    __syncthreads();
#pragma unroll
    for (int o = 1; o < 1024; o <<= 1) {
        int t = 0;
        if (threadIdx.x >= o) t = sm[threadIdx.x - o];
        __syncthreads();
        if (threadIdx.x >= o) sm[threadIdx.x] += t;
        __syncthreads();
    }
    if (i < N) g_rowstart[i] = sm[threadIdx.x] - v;  // exclusive within block
    if (threadIdx.x == 1023) g_part[blockIdx.x] = sm[1023];
}

__global__ void scan2_kernel(int nb) {
    if (threadIdx.x == 0) {
        int run = 0;
        for (int b = 0; b < nb; b++) {
            int v = g_part[b];
            g_part[b] = run;
            run += v;
        }
    }
}

__global__ void scan3_kernel(int N, int total) {
    int i = blockIdx.x * blockDim.x + threadIdx.x;
    if (i < N) {
        int v = g_rowstart[i] + g_part[i >> 10];
        g_rowstart[i] = v;
        g_cursor[i] = v;
    }
    if (i == 0) g_rowstart[N] = total;
}

// scatter edges into CSR order; compute layer-1 ee inline (both heads)
__global__ void scatter_kernel(const int* __restrict__ esrc, const int* __restrict__ edst,
                               int E, int N) {
    int t = blockIdx.x * blockDim.x + threadIdx.x;
    if (t >= E + N) return;
    int src, dst;
    if (t < E) { src = esrc[t]; dst = edst[t]; }
    else       { src = dst = t - E; }
    int pos = atomicAdd(&g_cursor[dst], 1);
    g_csr_src[pos] = src;
    float v0 = g_as1[src * 2]     + g_ad1[dst * 2];
    float v1 = g_as1[src * 2 + 1] + g_ad1[dst * 2 + 1];
    v0 = v0 > 0.f ? v0 : 0.2f * v0;
    v1 = v1 > 0.f ? v1 : 0.2f * v1;
    *(float2*)&g_ee1[pos * 2] = make_float2(__expf(v0), __expf(v1));
}

// ---------------- fp32 GEMM (f32x2 packed): Y[N,NC] = X[N,128] @ W[128,NC] ----------------
template <int NC>
__global__ void gemm_kernel(const float* __restrict__ X, const float* __restrict__ W,
                            float* __restrict__ Y, int N) {
    extern __shared__ float smem[];
    float* Xs = smem;               // 128 x 128
    float* Ws = smem + 128 * 128;   // 128 x NC
    const int tid = threadIdx.x;
    const int row0 = blockIdx.x * 128;

    for (int i = tid * 4; i < 128 * NC; i += 256 * 4)
        *(float4*)&Ws[i] = *(const float4*)&W[i];
    for (int i = tid * 4; i < 128 * 128; i += 256 * 4) {
        int r = i >> 7;
        int gr = row0 + r;
        float4 v = make_float4(0.f, 0.f, 0.f, 0.f);
        if (gr < N) v = *(const float4*)&X[gr * 128 + (i & 127)];
        *(float4*)&Xs[i] = v;
    }
    __syncthreads();

    constexpr int MC = NC / 16;   // 8 or 4 floats per thread per row
    constexpr int MH = MC / 2;    // u64 pairs
    const int tx = tid & 15, ty = tid >> 4;
    const int r0 = ty * 8, c0 = tx * MC;
    u64 acc[8][MH];
#pragma unroll
    for (int i = 0; i < 8; i++)
#pragma unroll
        for (int j = 0; j < MH; j++) acc[i][j] = pack2(0.f, 0.f);

#pragma unroll 4
    for (int k = 0; k < 128; k++) {
        float bb[MC];
#pragma unroll
        for (int j4 = 0; j4 < MC; j4 += 4)
            *(float4*)&bb[j4] = *(const float4*)&Ws[k * NC + c0 + j4];
        u64 bp[MH];
#pragma unroll
        for (int j = 0; j < MH; j++) bp[j] = pack2(bb[2 * j], bb[2 * j + 1]);
#pragma unroll
        for (int i = 0; i < 8; i++) {
            float a = Xs[(r0 + i) * 128 + k];
            u64 ap = pack2(a, a);
#pragma unroll
            for (int j = 0; j < MH; j++) fma2(acc[i][j], ap, bp[j]);
        }
    }

#pragma unroll
    for (int i = 0; i < 8; i++) {
        int gr = row0 + r0 + i;
        if (gr < N) {
            float outv[MC];
#pragma unroll
            for (int j = 0; j < MH; j++) unpack2(acc[i][j], outv[2 * j], outv[2 * j + 1]);
#pragma unroll
            for (int j4 = 0; j4 < MC; j4 += 4)
                *(float4*)&Y[gr * NC + c0 + j4] = *(const float4*)&outv[j4];
        }
    }
}

// ---------------- attention logits: alpha_s/alpha_d per (node, head) ----------------
__global__ void alpha_kernel(const float* __restrict__ h, const float* __restrict__ a_src,
                             const float* __restrict__ a_dst, float* __restrict__ out_s,
                             float* __restrict__ out_d, int N, int NH) {
    int t = blockIdx.x * blockDim.x + threadIdx.x;
    int g = t >> 4, li = t & 15;
    if (g >= N * NH) return;
    int head = (NH == 2) ? (g & 1) : 0;
    float4 hv = *(const float4*)&h[g * 64 + li * 4];
    float4 s4 = *(const float4*)&a_src[head * 64 + li * 4];
    float4 d4 = *(const float4*)&a_dst[head * 64 + li * 4];
    float s = hv.x * s4.x + hv.y * s4.y + hv.z * s4.z + hv.w * s4.w;
    float d = hv.x * d4.x + hv.y * d4.y + hv.z * d4.z + hv.w * d4.w;
#pragma unroll
    for (int o = 8; o; o >>= 1) {
        s += __shfl_down_sync(0xffffffffu, s, o, 16);
        d += __shfl_down_sync(0xffffffffu, d, o, 16);
    }
    if (li == 0) {
        out_s[g] = s;
        out_d[g] = d;
    }
}

// ---------------- layer1 aggregate: warp per dst, register accumulation, fused elu+bias ----------------
__global__ void agg1_kernel(const float* __restrict__ b1, int N) {
    int w = blockIdx.x * 8 + (threadIdx.x >> 5);
    int lane = threadIdx.x & 31;
    if (w >= N) return;
    int s0 = g_rowstart[w], s1 = g_rowstart[w + 1];
    const int head = lane >> 4;  // feats 0..63 = head0, 64..127 = head1
    float4 acc = make_float4(0.f, 0.f, 0.f, 0.f);
    float den0 = 0.f, den1 = 0.f;

    for (int base = s0; base < s1; base += 32) {
        int e = base + lane;
        int msrc = 0;
        float me0 = 0.f, me1 = 0.f;
        if (e < s1) {
            msrc = g_csr_src[e];
            float2 ee = *(const float2*)&g_ee1[e * 2];
            me0 = ee.x;
            me1 = ee.y;
        }
        den0 += me0;
        den1 += me1;
        int cnt = min(32, s1 - base);
        for (int j = 0; j < cnt; j++) {
            int s = __shfl_sync(0xffffffffu, msrc, j);
            float a0 = __shfl_sync(0xffffffffu, me0, j);
            float a1 = __shfl_sync(0xffffffffu, me1, j);
            float a = head ? a1 : a0;
            float4 v = *(const float4*)&g_h1[s * 128 + lane * 4];
            acc.x = fmaf(a, v.x, acc.x);
            acc.y = fmaf(a, v.y, acc.y);
            acc.z = fmaf(a, v.z, acc.z);
            acc.w = fmaf(a, v.w, acc.w);
        }
    }
#pragma unroll
    for (int o = 16; o; o >>= 1) {
        den0 += __shfl_xor_sync(0xffffffffu, den0, o);
        den1 += __shfl_xor_sync(0xffffffffu, den1, o);
    }
    float den = head ? den1 : den0;
    float rden = 1.f / den;
    float4 b = *(const float4*)&b1[lane * 4];
    float4 r;
    r.x = acc.x * rden + b.x;
    r.y = acc.y * rden + b.y;
    r.z = acc.z * rden + b.z;
    r.w = acc.w * rden + b.w;
    r.x = r.x > 0.f ? r.x : (__expf(r.x) - 1.f);
    r.y = r.y > 0.f ? r.y : (__expf(r.y) - 1.f);
    r.z = r.z > 0.f ? r.z : (__expf(r.z) - 1.f);
    r.w = r.w > 0.f ? r.w : (__expf(r.w) - 1.f);
    *(float4*)&g_z1[w * 128 + lane * 4] = r;
}

// ---------------- layer2 aggregate: warp per dst, ee computed inline, fused bias ----------------
__global__ void agg2_kernel(const float* __restrict__ as2, const float* __restrict__ ad2,
                            const float* __restrict__ b2, int N) {
    int w = blockIdx.x * 8 + (threadIdx.x >> 5);
    int lane = threadIdx.x & 31;
    if (w >= N) return;
    int s0 = g_rowstart[w], s1 = g_rowstart[w + 1];
    float add_d = ad2[w];
    float2 acc = make_float2(0.f, 0.f);
    float den = 0.f;

    for (int base = s0; base < s1; base += 32) {
        int e = base + lane;
        int msrc = 0;
        float mee = 0.f;
        if (e < s1) {
            msrc = g_csr_src[e];
            float v = as2[msrc] + add_d;
            v = v > 0.f ? v : 0.2f * v;
            mee = __expf(v);
        }
        den += mee;
        int cnt = min(32, s1 - base);
        for (int j = 0; j < cnt; j++) {
            int s = __shfl_sync(0xffffffffu, msrc, j);
            float a = __shfl_sync(0xffffffffu, mee, j);
            float2 v = *(const float2*)&g_h2[s * 64 + lane * 2];
            acc.x = fmaf(a, v.x, acc.x);
            acc.y = fmaf(a, v.y, acc.y);
        }
    }
#pragma unroll
    for (int o = 16; o; o >>= 1) den += __shfl_xor_sync(0xffffffffu, den, o);
    float rden = 1.f / den;
    float2 b = *(const float2*)&b2[lane * 2];
    float2 r;
    r.x = acc.x * rden + b.x;
    r.y = acc.y * rden + b.y;
    *(float2*)&g_z2[w * 64 + lane * 2] = r;
}

// ---------------- decode: dot(z2[a], z2[b]) over 64 ----------------
__global__ void decode_kernel(const int* __restrict__ eli, int EL, float* __restrict__ out) {
    int t = blockIdx.x * blockDim.x + threadIdx.x;
    int g = t >> 4, li = t & 15;
    if (g >= EL) return;
    int a = eli[g];
    int b = eli[EL + g];
    float4 va = *(const float4*)&g_z2[a * 64 + li * 4];
    float4 vb = *(const float4*)&g_z2[b * 64 + li * 4];
    float s = va.x * vb.x + va.y * vb.y + va.z * vb.z + va.w * vb.w;
#pragma unroll
    for (int o = 8; o; o >>= 1) s += __shfl_down_sync(0xffffffffu, s, o, 16);
    if (li == 0) out[g] = s;
}

// ---------------- launcher ----------------
extern "C" void kernel_launch(void* const* d_in, const int* in_sizes, int n_in,
                              void* d_out, int out_size) {
    const float* x   = (const float*)d_in[0];
    const int*   eidx = (const int*)d_in[1];
    const int*   eli  = (const int*)d_in[2];
    const float* W1  = (const float*)d_in[3];
    const float* as1 = (const float*)d_in[4];
    const float* ad1 = (const float*)d_in[5];
    const float* b1  = (const float*)d_in[6];
    const float* W2  = (const float*)d_in[7];
    const float* as2 = (const float*)d_in[8];
    const float* ad2 = (const float*)d_in[9];
    const float* b2  = (const float*)d_in[10];
    float* out = (float*)d_out;

    const int N  = in_sizes[0] / 128;
    const int E  = in_sizes[1] / 2;
    const int EL = in_sizes[2] / 2;
    const int* esrc = eidx;
    const int* edst = eidx + E;
    const int T = E + N;

    cudaFuncSetAttribute(gemm_kernel<128>, cudaFuncAttributeMaxDynamicSharedMemorySize, 131072);
    cudaFuncSetAttribute(gemm_kernel<64>,  cudaFuncAttributeMaxDynamicSharedMemorySize,  98304);

    float *ph1, *pz1, *ph2, *pas1, *pad1, *pas2, *pad2;
    cudaGetSymbolAddress((void**)&ph1,  g_h1);
    cudaGetSymbolAddress((void**)&pz1,  g_z1);
    cudaGetSymbolAddress((void**)&ph2,  g_h2);
    cudaGetSymbolAddress((void**)&pas1, g_as1);
    cudaGetSymbolAddress((void**)&pad1, g_ad1);
    cudaGetSymbolAddress((void**)&pas2, g_as2);
    cudaGetSymbolAddress((void**)&pad2, g_ad2);

    const int B = 256;
    auto cdiv = [](long long a, long long b) { return (int)((a + b - 1) / b); };
    const int nb = cdiv(N, 1024);

    // CSR structure (degree histogram + scan) — independent of features
    zero_deg_kernel<<<cdiv(N, B), B>>>(N);
    hist_kernel<<<cdiv(T, B), B>>>(edst, E, N);
    scan1_kernel<<<nb, 1024>>>(N);
    scan2_kernel<<<1, 32>>>(nb);
    scan3_kernel<<<cdiv(N, B), B>>>(N, T);

    // layer 1
    gemm_kernel<128><<<cdiv(N, 128), 256, 131072>>>(x, W1, ph1, N);
    alpha_kernel<<<cdiv((long long)N * 2 * 16, B), B>>>(ph1, as1, ad1, pas1, pad1, N, 2);
    scatter_kernel<<<cdiv(T, B), B>>>(esrc, edst, E, N);   // CSR src + ee1 (both heads)
    agg1_kernel<<<cdiv(N, 8), 256>>>(b1, N);               // -> g_z1 (elu fused)

    // layer 2
    gemm_kernel<64><<<cdiv(N, 128), 256, 98304>>>(pz1, W2, ph2, N);
    alpha_kernel<<<cdiv((long long)N * 16, B), B>>>(ph2, as2, ad2, pas2, pad2, N, 1);
    agg2_kernel<<<cdiv(N, 8), 256>>>(pas2, pad2, b2, N);   // ee2 inline -> g_z2

    // decode
    decode_kernel<<<cdiv((long long)EL * 16, B), B>>>(eli, EL, out);
}